// round 9
// baseline (speedup 1.0000x reference)
#include <cuda_runtime.h>
#include <math.h>

#define BB 16
#define CC 3
#define HH 512
#define WW 512
#define HWv (HH*WW)

#define TXW 128
#define TYH 16
#define NBLK (BB*(WW/TXW)*(HH/TYH))   // 2048
#define NT 512
#define PITCH 136          // col 3 = x-1 halo, 4..131 interior, 132 = x+128 halo
#define PS ((TYH+2)*PITCH) // plane size in floats (2448)
#define SMEM_BYTES (9*PS*4)  // 88128

#define IRBLK 64
#define NIRB (BB*IRBLK)    // 1024

__device__ double   g_ir_part[NIRB];
__device__ float    g_part[NBLK];
__device__ unsigned g_done = 0;

// ---------------------------------------------------------------------------
// 1) per-batch gray sum of input_ir. gray = 0.2989 R + 0.587 G + 0.114 B
// ---------------------------------------------------------------------------
__global__ __launch_bounds__(256)
void ir_mean_kernel(const float4* __restrict__ ir) {
    int b   = blockIdx.x / IRBLK;
    int blk = blockIdx.x % IRBLK;
    const int q4  = HWv / 4;
    const int per = q4 / IRBLK;       // 1024 float4 per block

    size_t base = (size_t)b * CC * q4 + (size_t)blk * per;
    const float4* r  = ir + base;
    const float4* g  = r + q4;
    const float4* bl = g + q4;

    float s = 0.f;
    #pragma unroll
    for (int i = threadIdx.x; i < per; i += 256) {
        float4 a = r[i], c = g[i], d = bl[i];
        s += 0.2989f * (a.x + a.y + a.z + a.w)
           + 0.587f  * (c.x + c.y + c.z + c.w)
           + 0.114f  * (d.x + d.y + d.z + d.w);
    }
    #pragma unroll
    for (int o = 16; o; o >>= 1) s += __shfl_down_sync(0xffffffffu, s, o);

    __shared__ float ws[8];
    int wid = threadIdx.x >> 5, lid = threadIdx.x & 31;
    if (lid == 0) ws[wid] = s;
    __syncthreads();
    if (wid == 0) {
        s = (lid < 8) ? ws[lid] : 0.f;
        #pragma unroll
        for (int o = 4; o; o >>= 1) s += __shfl_down_sync(0xffffffffu, s, o);
        if (lid == 0) g_ir_part[blockIdx.x] = (double)s;
    }
}

__device__ __forceinline__ float clip01(float x) {
    return fminf(fmaxf(x, 0.f), 1.f);
}

// Compute Sobel gx/gy for this thread's 4 pixels from one smem plane.
// Vertical partials in registers, horizontal halo of T/S via warp shuffle,
// edge lanes (0/31) pull the tile-halo columns from smem (predicated).
__device__ __forceinline__ void field_grad(const float* __restrict__ pl,
                                           int rbase, int cm, int lane,
                                           float gx[4], float gy[4], float ctr[4]) {
    const float* r0 = pl + rbase * PITCH + cm;
    const float* r1 = r0 + PITCH;
    const float* r2 = r1 + PITCH;
    float4 a = *(const float4*)r0;
    float4 b = *(const float4*)r1;
    float4 d = *(const float4*)r2;

    float T1 = a.x + 2.f*b.x + d.x, S1 = a.x - d.x;
    float T2 = a.y + 2.f*b.y + d.y, S2 = a.y - d.y;
    float T3 = a.z + 2.f*b.z + d.z, S3 = a.z - d.z;
    float T4 = a.w + 2.f*b.w + d.w, S4 = a.w - d.w;

    float Tl = 0.f, Sl = 0.f, Tr = 0.f, Sr = 0.f;
    if (lane == 0) {
        const float* h = pl + rbase * PITCH + 3;
        float e0 = h[0], e1 = h[PITCH], e2 = h[2*PITCH];
        Tl = e0 + 2.f*e1 + e2;  Sl = e0 - e2;
    }
    if (lane == 31) {
        const float* h = pl + rbase * PITCH + (4 + TXW);
        float e0 = h[0], e1 = h[PITCH], e2 = h[2*PITCH];
        Tr = e0 + 2.f*e1 + e2;  Sr = e0 - e2;
    }
    float tu = __shfl_up_sync(0xffffffffu, T4, 1);
    float su = __shfl_up_sync(0xffffffffu, S4, 1);
    float td = __shfl_down_sync(0xffffffffu, T1, 1);
    float sd = __shfl_down_sync(0xffffffffu, S1, 1);
    float T0 = lane ? tu : Tl;
    float S0 = lane ? su : Sl;
    float T5 = (lane < 31) ? td : Tr;
    float S5 = (lane < 31) ? sd : Sr;

    gx[0] = T2 - T0;  gx[1] = T3 - T1;  gx[2] = T4 - T2;  gx[3] = T5 - T3;
    gy[0] = S0 + 2.f*S1 + S2;  gy[1] = S1 + 2.f*S2 + S3;
    gy[2] = S2 + 2.f*S3 + S4;  gy[3] = S3 + 2.f*S4 + S5;
    ctr[0] = b.x;  ctr[1] = b.y;  ctr[2] = b.z;  ctr[3] = b.w;
}

// ---------------------------------------------------------------------------
// 2) fused main pass: one load phase (all 3 channels, 9 planes), one sync,
//    shuffle-based stencil compute, fused grid-final reduction.
// ---------------------------------------------------------------------------
extern __shared__ float smq[];

__global__ __launch_bounds__(NT, 2)
void fusion_main_kernel(const float* __restrict__ vis,
                        const float* __restrict__ ir,
                        const float* __restrict__ outp,
                        const float* __restrict__ mask,
                        float* __restrict__ out) {
    __shared__ double dred[2];
    __shared__ float  s_mean;
    __shared__ float  ws[NT / 32];
    __shared__ double wd[NT / 32];
    __shared__ bool   s_last;

    const int tid = threadIdx.x;
    const int bx  = blockIdx.x;
    const int b   = bx >> 7;
    const int rem = bx & 127;
    const int y0  = (rem >> 2) * TYH;
    const int w0  = (rem & 3) * TXW;

    // per-batch IR mean from 64 partials
    if (tid < IRBLK) {
        double s = g_ir_part[b * IRBLK + tid];
        #pragma unroll
        for (int o = 16; o; o >>= 1) s += __shfl_down_sync(0xffffffffu, s, o);
        if ((tid & 31) == 0) dred[tid >> 5] = s;
    }
    __syncthreads();
    if (tid == 0) s_mean = (float)((dred[0] + dred[1]) * (1.0 / (double)HWv));
    __syncthreads();
    const float meanb = s_mean;

    // ---------------- load phase: all 3 channels, no intermediate syncs ----
    #pragma unroll
    for (int c = 0; c < CC; c++) {
        const size_t pbase = ((size_t)b * CC + c) * HWv;
        float* pF = smq + (c * 3 + 0) * PS;
        float* pV = smq + (c * 3 + 1) * PS;
        float* pI = smq + (c * 3 + 2) * PS;

        for (int idx = tid; idx < 612; idx += NT) {
            if (idx < 576) {
                int hy = idx >> 5, k = idx & 31;
                int y = y0 - 1 + hy;
                float4 f = make_float4(0.f, 0.f, 0.f, 0.f), v = f, q = f;
                if ((unsigned)y < HH) {
                    size_t rowp = pbase + (size_t)y * WW + w0;
                    float4 a  = ((const float4*)(outp + rowp))[k];
                    float4 m  = ((const float4*)(mask + rowp))[k];
                    float4 vv = ((const float4*)(vis  + rowp))[k];
                    float4 qq = ((const float4*)(ir   + rowp))[k];
                    f = make_float4(a.x * m.x, a.y * m.y, a.z * m.z, a.w * m.w);
                    v = make_float4(clip01(sqrtf(vv.x)), clip01(sqrtf(vv.y)),
                                    clip01(sqrtf(vv.z)), clip01(sqrtf(vv.w)));
                    q = make_float4(clip01(1.8f * qq.x - 0.8f * meanb),
                                    clip01(1.8f * qq.y - 0.8f * meanb),
                                    clip01(1.8f * qq.z - 0.8f * meanb),
                                    clip01(1.8f * qq.w - 0.8f * meanb));
                }
                int off = hy * PITCH + 4 + 4 * k;
                *(float4*)&pF[off] = f;
                *(float4*)&pV[off] = v;
                *(float4*)&pI[off] = q;
            } else {
                int j = idx - 576;
                int hy = j >> 1, side = j & 1;
                int y = y0 - 1 + hy;
                int x = side ? (w0 + TXW) : (w0 - 1);
                float f = 0.f, v = 0.f, q = 0.f;
                if ((unsigned)y < HH && (unsigned)x < WW) {
                    size_t p = pbase + (size_t)y * WW + x;
                    f = outp[p] * mask[p];
                    v = clip01(sqrtf(vis[p]));
                    q = clip01(1.8f * ir[p] - 0.8f * meanb);
                }
                int off = hy * PITCH + (side ? (4 + TXW) : 3);
                pF[off] = f;  pV[off] = v;  pI[off] = q;
            }
        }
    }
    __syncthreads();

    // ---------------- compute phase ---------------------------------------
    const int row  = tid >> 5;       // 0..15 : this thread's pixel row
    const int lane = tid & 31;
    const int cm   = 4 + lane * 4;   // aligned interior column

    float con = 0.f, gsum = 0.f, color = 0.f;
    float d0[4], dy[4];

    #pragma unroll
    for (int c = 0; c < CC; c++) {
        const float* plF = smq + (c * 3 + 0) * PS;
        const float* plV = smq + (c * 3 + 1) * PS;
        const float* plI = smq + (c * 3 + 2) * PS;

        float igx[4], igy[4], Ic[4];
        field_grad(plI, row, cm, lane, igx, igy, Ic);
        float vgx[4], vgy[4], Vc[4];
        field_grad(plV, row, cm, lane, vgx, vgy, Vc);
        #pragma unroll
        for (int j = 0; j < 4; j++) {
            igx[j] = fmaxf(igx[j], vgx[j]);
            igy[j] = fmaxf(igy[j], vgy[j]);
            Ic[j]  = fmaxf(Ic[j],  Vc[j]);   // joint intensity
        }
        float fgx[4], fgy[4], Fc[4];
        field_grad(plF, row, cm, lane, fgx, fgy, Fc);
        #pragma unroll
        for (int j = 0; j < 4; j++) {
            gsum += fabsf(fgx[j] - igx[j]) + fabsf(fgy[j] - igy[j]);
            con  += fabsf(Fc[j] - Ic[j]);
            float d = Fc[j] - Vc[j];
            if (c == 0)      { d0[j] = d; dy[j] = 0.299f * d; }
            else if (c == 1) { dy[j] += 0.587f * d; }
            else {
                float dyt = dy[j] + 0.114f * d;
                color += 0.564f * fabsf(d - dyt) + 0.713f * fabsf(d0[j] - dyt);
            }
        }
    }

    const float inv3 = 1.0f / (float)(BB * CC * HWv);
    const float inv1 = 1.0f / (float)(BB * HWv);
    float acc = inv3 * (0.5f * con + 0.1f * gsum) + inv1 * color;

    // block reduction -> per-block partial
    #pragma unroll
    for (int o = 16; o; o >>= 1) acc += __shfl_down_sync(0xffffffffu, acc, o);
    int wid = tid >> 5, lid = tid & 31;
    if (lid == 0) ws[wid] = acc;
    __syncthreads();
    if (wid == 0) {
        acc = (lid < NT / 32) ? ws[lid] : 0.f;
        #pragma unroll
        for (int o = 8; o; o >>= 1) acc += __shfl_down_sync(0xffffffffu, acc, o);
        if (lid == 0) g_part[bx] = acc;
    }

    // fused finalize: last block sums all partials
    __threadfence();
    if (tid == 0) s_last = (atomicAdd(&g_done, 1u) == NBLK - 1);
    __syncthreads();
    if (s_last) {
        double s = 0.0;
        #pragma unroll
        for (int i = 0; i < NBLK / NT; i++) s += (double)g_part[tid + i * NT];
        #pragma unroll
        for (int o = 16; o; o >>= 1) s += __shfl_down_sync(0xffffffffu, s, o);
        if (lid == 0) wd[wid] = s;
        __syncthreads();
        if (wid == 0) {
            s = (lid < NT / 32) ? wd[lid] : 0.0;
            #pragma unroll
            for (int o = 8; o; o >>= 1) s += __shfl_down_sync(0xffffffffu, s, o);
            if (lid == 0) { out[0] = (float)s; g_done = 0; }
        }
    }
}

extern "C" void kernel_launch(void* const* d_in, const int* in_sizes, int n_in,
                              void* d_out, int out_size) {
    const float* vis  = (const float*)d_in[0];
    const float* ir   = (const float*)d_in[1];
    const float* outp = (const float*)d_in[2];
    const float* mask = (const float*)d_in[3];
    float* out = (float*)d_out;

    cudaFuncSetAttribute(fusion_main_kernel,
                         cudaFuncAttributeMaxDynamicSharedMemorySize, SMEM_BYTES);

    ir_mean_kernel<<<NIRB, 256>>>((const float4*)ir);
    fusion_main_kernel<<<NBLK, NT, SMEM_BYTES>>>(vis, ir, outp, mask, out);
}

// round 11
// speedup vs baseline: 1.4711x; 1.4711x over previous
#include <cuda_runtime.h>
#include <math.h>

#define BB 16
#define CC 3
#define HH 512
#define WW 512
#define HWv (HH*WW)

#define TXW 128
#define TYH 8
#define XT (WW/TXW)           // 4
#define YT (HH/TYH)           // 64
#define NBLK (BB*XT*YT)       // 4096
#define NT 256
#define PITCH 136             // col 3 = x-1 halo, 4..131 interior, 132 = x+128 halo

#define IRBLK 128
#define NIRB (BB*IRBLK)       // 2048

__device__ double   g_ir_part[NIRB];
__device__ float    g_part[NBLK];
__device__ unsigned g_done = 0;

// ---------------------------------------------------------------------------
// 1) per-batch gray sum of input_ir. gray = 0.2989 R + 0.587 G + 0.114 B
// ---------------------------------------------------------------------------
__global__ __launch_bounds__(256)
void ir_mean_kernel(const float4* __restrict__ ir) {
    int b   = blockIdx.x / IRBLK;
    int blk = blockIdx.x % IRBLK;
    const int q4  = HWv / 4;
    const int per = q4 / IRBLK;       // 512 float4 per block

    size_t base = (size_t)b * CC * q4 + (size_t)blk * per;
    const float4* r  = ir + base;
    const float4* g  = r + q4;
    const float4* bl = g + q4;

    float s = 0.f;
    #pragma unroll
    for (int i = threadIdx.x; i < per; i += 256) {
        float4 a = r[i], c = g[i], d = bl[i];
        s += 0.2989f * (a.x + a.y + a.z + a.w)
           + 0.587f  * (c.x + c.y + c.z + c.w)
           + 0.114f  * (d.x + d.y + d.z + d.w);
    }
    #pragma unroll
    for (int o = 16; o; o >>= 1) s += __shfl_down_sync(0xffffffffu, s, o);

    __shared__ float ws[8];
    int wid = threadIdx.x >> 5, lid = threadIdx.x & 31;
    if (lid == 0) ws[wid] = s;
    __syncthreads();
    if (wid == 0) {
        s = (lid < 8) ? ws[lid] : 0.f;
        #pragma unroll
        for (int o = 4; o; o >>= 1) s += __shfl_down_sync(0xffffffffu, s, o);
        if (lid == 0) g_ir_part[blockIdx.x] = (double)s;
    }
}

__device__ __forceinline__ float clip01(float x) {
    return fminf(fmaxf(x, 0.f), 1.f);
}

// ---------------------------------------------------------------------------
// 2) fused main pass: 128x8 tiles, per-channel load/compute phases (R8
//    structure), 4 resident blocks/SM for cross-block phase overlap.
// ---------------------------------------------------------------------------
__global__ __launch_bounds__(NT, 4)
void fusion_main_kernel(const float* __restrict__ vis,
                        const float* __restrict__ ir,
                        const float* __restrict__ outp,
                        const float* __restrict__ mask,
                        float* __restrict__ out) {
    __shared__ __align__(16) float sF[TYH + 2][PITCH];
    __shared__ __align__(16) float sV[TYH + 2][PITCH];
    __shared__ __align__(16) float sI[TYH + 2][PITCH];
    __shared__ double dred[4];
    __shared__ float  s_mean;
    __shared__ float  ws[NT / 32];
    __shared__ double wd[NT / 32];
    __shared__ bool   s_last;

    const int tid = threadIdx.x;
    const int bx  = blockIdx.x;
    const int b   = bx >> 8;              // 256 tiles per batch
    const int rem = bx & 255;
    const int y0  = (rem >> 2) * TYH;
    const int w0  = (rem & 3) * TXW;

    // per-batch IR mean from 128 partials
    if (tid < IRBLK) {
        double s = g_ir_part[b * IRBLK + tid];
        #pragma unroll
        for (int o = 16; o; o >>= 1) s += __shfl_down_sync(0xffffffffu, s, o);
        if ((tid & 31) == 0) dred[tid >> 5] = s;
    }
    __syncthreads();
    if (tid == 0)
        s_mean = (float)((dred[0] + dred[1] + dred[2] + dred[3]) * (1.0 / (double)HWv));
    __syncthreads();
    const float meanb = s_mean;

    const int dx = tid & 127;             // x within tile
    const int rg = tid >> 7;              // rowgroup 0..1 -> rows 4rg..4rg+3
    const int cm = dx + 4;                // smem mid column
    const int hb = rg * 4;                // first window smem row

    float con = 0.f, gsum = 0.f, color = 0.f;
    float d0[4], dyk[4];

    #pragma unroll
    for (int c = 0; c < CC; c++) {
        const size_t pbase = ((size_t)b * CC + c) * HWv;

        // ---- load 10x128 interior (float4) + 10x2 halo scalars ----
        for (int idx = tid; idx < 340; idx += NT) {
            if (idx < 320) {
                int hy = idx >> 5, k = idx & 31;
                int y = y0 - 1 + hy;
                float4 f = make_float4(0.f, 0.f, 0.f, 0.f), v = f, q = f;
                if ((unsigned)y < HH) {
                    size_t rowp = pbase + (size_t)y * WW + w0;
                    float4 a  = ((const float4*)(outp + rowp))[k];
                    float4 m  = ((const float4*)(mask + rowp))[k];
                    float4 vv = ((const float4*)(vis  + rowp))[k];
                    float4 qq = ((const float4*)(ir   + rowp))[k];
                    f = make_float4(a.x * m.x, a.y * m.y, a.z * m.z, a.w * m.w);
                    v = make_float4(clip01(sqrtf(vv.x)), clip01(sqrtf(vv.y)),
                                    clip01(sqrtf(vv.z)), clip01(sqrtf(vv.w)));
                    q = make_float4(clip01(1.8f * qq.x - 0.8f * meanb),
                                    clip01(1.8f * qq.y - 0.8f * meanb),
                                    clip01(1.8f * qq.z - 0.8f * meanb),
                                    clip01(1.8f * qq.w - 0.8f * meanb));
                }
                *(float4*)&sF[hy][4 + 4 * k] = f;
                *(float4*)&sV[hy][4 + 4 * k] = v;
                *(float4*)&sI[hy][4 + 4 * k] = q;
            } else {
                int j = idx - 320;
                int hy = j >> 1, side = j & 1;
                int y = y0 - 1 + hy;
                int x = side ? (w0 + TXW) : (w0 - 1);
                float f = 0.f, v = 0.f, q = 0.f;
                if ((unsigned)y < HH && (unsigned)x < WW) {
                    size_t p = pbase + (size_t)y * WW + x;
                    f = outp[p] * mask[p];
                    v = clip01(sqrtf(vis[p]));
                    q = clip01(1.8f * ir[p] - 0.8f * meanb);
                }
                int cp = side ? (4 + TXW) : 3;
                sF[hy][cp] = f; sV[hy][cp] = v; sI[hy][cp] = q;
            }
        }
        __syncthreads();

        // ---- compute: rolling 3x3 windows over smem rows hb..hb+5 ----
        float wF[3][3], wV[3][3], wI[3][3];
        #pragma unroll
        for (int r = 0; r < 2; r++) {
            wF[r][0] = sF[hb + r][cm - 1]; wF[r][1] = sF[hb + r][cm]; wF[r][2] = sF[hb + r][cm + 1];
            wV[r][0] = sV[hb + r][cm - 1]; wV[r][1] = sV[hb + r][cm]; wV[r][2] = sV[hb + r][cm + 1];
            wI[r][0] = sI[hb + r][cm - 1]; wI[r][1] = sI[hb + r][cm]; wI[r][2] = sI[hb + r][cm + 1];
        }
        #pragma unroll
        for (int k = 0; k < 4; k++) {
            const int rp = k % 3, rq = (k + 1) % 3, rn = (k + 2) % 3;
            const int hy = hb + k + 2;
            wF[rn][0] = sF[hy][cm - 1]; wF[rn][1] = sF[hy][cm]; wF[rn][2] = sF[hy][cm + 1];
            wV[rn][0] = sV[hy][cm - 1]; wV[rn][1] = sV[hy][cm]; wV[rn][2] = sV[hy][cm + 1];
            wI[rn][0] = sI[hy][cm - 1]; wI[rn][1] = sI[hy][cm]; wI[rn][2] = sI[hy][cm + 1];

            float fgx = (wF[rp][2] + 2.f * wF[rq][2] + wF[rn][2]) - (wF[rp][0] + 2.f * wF[rq][0] + wF[rn][0]);
            float vgx = (wV[rp][2] + 2.f * wV[rq][2] + wV[rn][2]) - (wV[rp][0] + 2.f * wV[rq][0] + wV[rn][0]);
            float igx = (wI[rp][2] + 2.f * wI[rq][2] + wI[rn][2]) - (wI[rp][0] + 2.f * wI[rq][0] + wI[rn][0]);
            float fgy = (wF[rp][0] - wF[rn][0]) + 2.f * (wF[rp][1] - wF[rn][1]) + (wF[rp][2] - wF[rn][2]);
            float vgy = (wV[rp][0] - wV[rn][0]) + 2.f * (wV[rp][1] - wV[rn][1]) + (wV[rp][2] - wV[rn][2]);
            float igy = (wI[rp][0] - wI[rn][0]) + 2.f * (wI[rp][1] - wI[rn][1]) + (wI[rp][2] - wI[rn][2]);

            gsum += fabsf(fgx - fmaxf(vgx, igx)) + fabsf(fgy - fmaxf(vgy, igy));

            float Fc = wF[rq][1], Vc = wV[rq][1];
            con += fabsf(Fc - fmaxf(Vc, wI[rq][1]));

            float d = Fc - Vc;
            if (c == 0)      { d0[k] = d; dyk[k] = 0.299f * d; }
            else if (c == 1) { dyk[k] += 0.587f * d; }
            else {
                float dyt = dyk[k] + 0.114f * d;
                color += 0.564f * fabsf(d - dyt) + 0.713f * fabsf(d0[k] - dyt);
            }
        }
        __syncthreads();
    }

    const float inv3 = 1.0f / (float)(BB * CC * HWv);
    const float inv1 = 1.0f / (float)(BB * HWv);
    float acc = inv3 * (0.5f * con + 0.1f * gsum) + inv1 * color;

    // block reduction -> per-block partial
    #pragma unroll
    for (int o = 16; o; o >>= 1) acc += __shfl_down_sync(0xffffffffu, acc, o);
    int wid = tid >> 5, lid = tid & 31;
    if (lid == 0) ws[wid] = acc;
    __syncthreads();
    if (wid == 0) {
        acc = (lid < NT / 32) ? ws[lid] : 0.f;
        #pragma unroll
        for (int o = 4; o; o >>= 1) acc += __shfl_down_sync(0xffffffffu, acc, o);
        if (lid == 0) g_part[bx] = acc;
    }

    // fused finalize: last block sums all partials
    __threadfence();
    if (tid == 0) s_last = (atomicAdd(&g_done, 1u) == NBLK - 1);
    __syncthreads();
    if (s_last) {
        double s = 0.0;
        #pragma unroll
        for (int i = 0; i < NBLK / NT; i++) s += (double)g_part[tid + i * NT];
        #pragma unroll
        for (int o = 16; o; o >>= 1) s += __shfl_down_sync(0xffffffffu, s, o);
        if (lid == 0) wd[wid] = s;
        __syncthreads();
        if (wid == 0) {
            s = (lid < NT / 32) ? wd[lid] : 0.0;
            #pragma unroll
            for (int o = 4; o; o >>= 1) s += __shfl_down_sync(0xffffffffu, s, o);
            if (lid == 0) { out[0] = (float)s; g_done = 0; }
        }
    }
}

extern "C" void kernel_launch(void* const* d_in, const int* in_sizes, int n_in,
                              void* d_out, int out_size) {
    const float* vis  = (const float*)d_in[0];
    const float* ir   = (const float*)d_in[1];
    const float* outp = (const float*)d_in[2];
    const float* mask = (const float*)d_in[3];
    float* out = (float*)d_out;

    ir_mean_kernel<<<NIRB, 256>>>((const float4*)ir);
    fusion_main_kernel<<<NBLK, NT>>>(vis, ir, outp, mask, out);
}